// round 14
// baseline (speedup 1.0000x reference)
#include <cuda_runtime.h>
#include <cuda_fp16.h>
#include <math.h>

#define T_DIM 2048
#define B_DIM 1024
#define A_DIM 4
#define D_DIM 128
#define P_DIM 256
#define TC    16
#define NCH   (T_DIM / TC)     // 128 chunks of 64 rows
#define LDB   272              // tile row stride in bytes (136 halves)
#define NLOGIT (T_DIM * B_DIM * A_DIM)

// SMEM layout (bytes) — total 74368 => 3 CTAs/SM
#define OFF_SA    0            // 2 x 64 float2   [0,1024)
#define OFF_BETA  1024         // 128 floats      [1024,1536)
#define OFF_LPART 1536         // 4 x 64 floats   [1536,2560)
#define OFF_CT    2560         // 136 x 272 = 36992  [2560,39552)
#define OFF_HS    39552        // 64 x 272 = 17408   [39552,56960)
#define OFF_QS    56960        // 17408              [56960,74368)
#define SMEM_BYTES 74368

// scratch: per (b,t,a): (s = r*a, a)
__device__ float2 g_SA[(size_t)B_DIM * T_DIM * A_DIM];

static __device__ __forceinline__ float nan0(float x) { return (x == x) ? x : 0.0f; }
static __device__ __forceinline__ float clipf(float x, float lo, float hi) {
    return fminf(fmaxf(x, lo), hi);
}
static __device__ __forceinline__ unsigned smem_u32(const void* p) {
    return (unsigned)__cvta_generic_to_shared(p);
}

__global__ void prep_kernel(const float* __restrict__ inp) {
    int gid = blockIdx.x * blockDim.x + threadIdx.x;
    if (gid >= T_DIM * B_DIM) return;
    int b = gid % B_DIM;
    int t = gid / B_DIM;
    const float* row = inp + ((size_t)t * B_DIM + b) * 9;
    float2* o = g_SA + ((size_t)b * T_DIM + t) * A_DIM;
#pragma unroll
    for (int a = 0; a < A_DIM; a++) {
        float act = nan0(row[a]);
        float r   = nan0(row[4 + a]);
        o[a] = make_float2(r * act, act);
    }
}

static __device__ __forceinline__ void mma16816(float* acc, const unsigned* a,
                                                unsigned b0, unsigned b1) {
    asm volatile(
        "mma.sync.aligned.m16n8k16.row.col.f32.f16.f16.f32 "
        "{%0,%1,%2,%3}, {%4,%5,%6,%7}, {%8,%9}, {%0,%1,%2,%3};\n"
        : "+f"(acc[0]), "+f"(acc[1]), "+f"(acc[2]), "+f"(acc[3])
        : "r"(a[0]), "r"(a[1]), "r"(a[2]), "r"(a[3]), "r"(b0), "r"(b1));
}
static __device__ __forceinline__ void ldsm4(unsigned* r, unsigned addr) {
    asm volatile(
        "ldmatrix.sync.aligned.m8n8.x4.shared.b16 {%0,%1,%2,%3}, [%4];\n"
        : "=r"(r[0]), "=r"(r[1]), "=r"(r[2]), "=r"(r[3]) : "r"(addr));
}
static __device__ __forceinline__ void ldsm2(unsigned* r, unsigned addr) {
    asm volatile(
        "ldmatrix.sync.aligned.m8n8.x2.shared.b16 {%0,%1}, [%2];\n"
        : "=r"(r[0]), "=r"(r[1]) : "r"(addr));
}

// ---------------------------------------------------------------------------
// ONE CTA per b, 256 threads (8 warps), 3 CTAs/SM (smem 72.6KB, regs<=85).
// TC=16 (64-row chunks), SINGLE-buffered tiles, phased scan -> GEMM.
// Warp tile 32 rows (mwg=w&1) x 32 cols (nwg=w>>1); B from SMEM.
// kappa FOLDED INTO GEMM: Ct row 128 = kappa => U[:,128] = kappa.h,
// computed by the two nwg==0 warps (accx).  No epilogue H reads.
// ---------------------------------------------------------------------------
__global__ void __launch_bounds__(256, 3) gql_main(
    const float* __restrict__ inp,
    const float* __restrict__ phi_raw,  const float* __restrict__ chi_raw,
    const float* __restrict__ beta_raw, const float* __restrict__ kappa_raw,
    const float* __restrict__ C_raw,    float* __restrict__ out) {
    extern __shared__ char sm[];
    float2* sa_s   = (float2*)(sm + OFF_SA);
    float*  beta_s = (float*)(sm + OFF_BETA);
    float*  lpart  = (float*)(sm + OFF_LPART);
    __half* Ct     = (__half*)(sm + OFF_CT);

    const int b    = blockIdx.x;
    const int tid  = threadIdx.x;
    const int lane = tid & 31;
    const int w    = tid >> 5;
    const int g    = lane >> 2;
    const int tg   = lane & 3;
    const int pid  = min(max((int)nan0(__ldg(inp + (size_t)b * 9 + 8)), 0), P_DIM - 1);

    // scan assignment: a = tid>>6, d-pair (d0, d0+1)
    const int aidx = tid >> 6;
    const int d2   = tid & 63;
    const int d0   = d2 * 2;

    float phr0 = phi_raw[pid * D_DIM + d0], phr1 = phi_raw[pid * D_DIM + d0 + 1];
    float chr0 = chi_raw[pid * D_DIM + d0], chr1 = chi_raw[pid * D_DIM + d0 + 1];
    float phi0 = clipf(1.0f / (1.0f + expf(-phr0)), 0.01f, 0.99f);
    float phi1 = clipf(1.0f / (1.0f + expf(-phr1)), 0.01f, 0.99f);
    float chi0 = clipf(1.0f / (1.0f + expf(-chr0)), 0.01f, 0.99f);
    float chi1 = clipf(1.0f / (1.0f + expf(-chr1)), 0.01f, 0.99f);
    float omp0 = 1.0f - phi0, omp1 = 1.0f - phi1;
    float omc0 = 1.0f - chi0, omc1 = 1.0f - chi1;

    // zero Ct rows 128..135 (kappa N-tile), then sync before kappa lands
    for (int i = tid; i < (8 * LDB) / 4; i += 256)
        ((unsigned*)(sm + OFF_CT + 128 * LDB))[i] = 0;
    __syncthreads();
    if (tid < 128) {
        float br = beta_raw[pid * D_DIM + tid];
        float sp = fmaxf(br, 0.0f) + log1pf(expf(-fabsf(br)));
        beta_s[tid] = clipf(sp, 0.1f, 10.0f);
        Ct[128 * 136 + tid] =
            __float2half(clipf(kappa_raw[pid * D_DIM + tid], -10.0f, 10.0f));
    }
    // Ct[e][d] = clip(C[d][e])  (col-major B operand), stays in SMEM
    for (int i = tid; i < D_DIM * D_DIM; i += 256) {
        int d = i >> 7, e = i & 127;
        Ct[e * 136 + d] = __float2half(clipf(C_raw[(size_t)pid * (D_DIM * D_DIM) + i],
                                             -10.0f, 10.0f));
    }

    // preload sa chunk 0 into buf 0
    const float2* sa_src = g_SA + (size_t)b * T_DIM * A_DIM;
    if (tid < 64) sa_s[tid] = sa_src[tid];
    __syncthreads();

    // warp tiling + fragment addresses
    const int mwg = w & 1;
    const int nwg = w >> 1;
    const bool kon = (nwg == 0);   // these warps also compute the kappa column
    const unsigned amt = smem_u32(sm + OFF_HS)
        + (unsigned)((mwg * 32 + (lane & 15)) * LDB + ((lane & 16) ? 16 : 0));
    const unsigned bb = smem_u32(Ct)
        + (unsigned)((nwg * 32 + (lane & 7) + ((lane & 16) ? 8 : 0)) * LDB
                     + ((lane & 8) ? 16 : 0));
    const unsigned bbx = smem_u32(Ct)
        + (unsigned)((128 + (lane & 7)) * LDB + ((lane & 8) ? 16 : 0));
    const unsigned qb = smem_u32(sm + OFF_QS) + (unsigned)((mwg * 32 + lane) * LDB);

    float q0 = 0.5f, q1 = 0.5f, h0 = 0.0f, h1 = 0.0f;

    for (int c = 0; c < NCH; c++) {
        const int cb = c & 1;
        float2 nxt;
        const bool pf = (tid < 64) && (c + 1 < NCH);
        if (pf) nxt = __ldg(sa_src + (c + 1) * 64 + tid);

        // ---- scan phase: fp32 state -> f16 tiles ----
        {
            char* Hw = sm + OFF_HS;
            char* Qw = sm + OFF_QS;
            const float2* sab = sa_s + cb * 64;
#pragma unroll 4
            for (int tt = 0; tt < TC; tt++) {
                float2 sa = sab[tt * 4 + aidx];
                q0 = omp0 * q0 + phi0 * sa.x;
                q1 = omp1 * q1 + phi1 * sa.x;
                h0 = omc0 * h0 + chi0 * sa.y;
                h1 = omc1 * h1 + chi1 * sa.y;
                int row = tt * 4 + aidx;
                *(__half2*)(Hw + row * LDB + d2 * 4) = __floats2half2_rn(h0, h1);
                *(__half2*)(Qw + row * LDB + d2 * 4) = __floats2half2_rn(q0, q1);
            }
        }
        if (pf) sa_s[(cb ^ 1) * 64 + tid] = nxt;
        __syncthreads();   // tiles + next sa ready

        // ---- GEMM: 32x32 warp tile (+ kappa column on kon warps) ----
        float acc[2][4][4];
        float accx[2][4];
#pragma unroll
        for (int mt = 0; mt < 2; mt++) {
#pragma unroll
            for (int nt = 0; nt < 4; nt++)
#pragma unroll
                for (int i = 0; i < 4; i++) acc[mt][nt][i] = 0.0f;
#pragma unroll
            for (int i = 0; i < 4; i++) accx[mt][i] = 0.0f;
        }

#pragma unroll
        for (int ks = 0; ks < 8; ks++) {
            unsigned af0[4], af1[4], bf[4];
            ldsm4(af0, amt + ks * 32);
            ldsm4(af1, amt + 16 * LDB + ks * 32);
            ldsm4(bf, bb + ks * 32);
            mma16816(acc[0][0], af0, bf[0], bf[1]);
            mma16816(acc[0][1], af0, bf[2], bf[3]);
            mma16816(acc[1][0], af1, bf[0], bf[1]);
            mma16816(acc[1][1], af1, bf[2], bf[3]);
            ldsm4(bf, bb + 16 * LDB + ks * 32);
            mma16816(acc[0][2], af0, bf[0], bf[1]);
            mma16816(acc[0][3], af0, bf[2], bf[3]);
            mma16816(acc[1][2], af1, bf[0], bf[1]);
            mma16816(acc[1][3], af1, bf[2], bf[3]);
            if (kon) {
                unsigned bfx[2];
                ldsm2(bfx, bbx + ks * 32);
                mma16816(accx[0], af0, bfx[0], bfx[1]);
                mma16816(accx[1], af1, bfx[0], bfx[1]);
            }
        }

        // ---- epilogue: logit partials over this warp's 32 cols ----
        float pl0[2] = {0.f, 0.f}, pl1[2] = {0.f, 0.f};
#pragma unroll
        for (int nt = 0; nt < 4; nt++) {
            int col = nwg * 32 + nt * 8;
            float2 bet = make_float2(beta_s[col + 2 * tg], beta_s[col + 2 * tg + 1]);
            unsigned qf[4];
            ldsm4(qf, qb + (unsigned)(col * 2));
#pragma unroll
            for (int mt = 0; mt < 2; mt++) {
                float2 qv0 = __half22float2(*(__half2*)&qf[2 * mt]);
                float2 qv1 = __half22float2(*(__half2*)&qf[2 * mt + 1]);
                pl0[mt] += (acc[mt][nt][0] + bet.x) * qv0.x
                         + (acc[mt][nt][1] + bet.y) * qv0.y;
                pl1[mt] += (acc[mt][nt][2] + bet.x) * qv1.x
                         + (acc[mt][nt][3] + bet.y) * qv1.y;
            }
        }
#pragma unroll
        for (int mt = 0; mt < 2; mt++) {
            if (kon && tg == 0) {     // kappa column (U[:,128]) contribution
                pl0[mt] += accx[mt][0];
                pl1[mt] += accx[mt][2];
            }
            pl0[mt] += __shfl_xor_sync(0xffffffffu, pl0[mt], 1);
            pl0[mt] += __shfl_xor_sync(0xffffffffu, pl0[mt], 2);
            pl1[mt] += __shfl_xor_sync(0xffffffffu, pl1[mt], 1);
            pl1[mt] += __shfl_xor_sync(0xffffffffu, pl1[mt], 2);
            if (tg == 0) {
                int r0 = mwg * 32 + mt * 16 + g;
                lpart[nwg * 64 + r0]     = pl0[mt];
                lpart[nwg * 64 + r0 + 8] = pl1[mt];
            }
        }
        __syncthreads();   // lpart ready; tiles consumed (safe for next scan)

        if (tid < 64) {    // combine 4 col-group partials, store logits
            float lg = (lpart[tid] + lpart[64 + tid])
                     + (lpart[128 + tid] + lpart[192 + tid]);
            int tt = tid >> 2, a = tid & 3;
            out[((size_t)(c * TC + tt) * B_DIM + b) * A_DIM + a] = lg;
        }
        // next lpart write happens only after the next __syncthreads()
    }

    // final q, h: shape (B, A, D)
    float* out_q = out + (size_t)NLOGIT;
    float* out_h = out_q + B_DIM * A_DIM * D_DIM;
    ((float2*)out_q)[(b * A_DIM + aidx) * 64 + d2] = make_float2(q0, q1);
    ((float2*)out_h)[(b * A_DIM + aidx) * 64 + d2] = make_float2(h0, h1);
}

extern "C" void kernel_launch(void* const* d_in, const int* in_sizes, int n_in,
                              void* d_out, int out_size) {
    const float* inp       = (const float*)d_in[0];
    const float* phi_raw   = (const float*)d_in[1];
    const float* chi_raw   = (const float*)d_in[2];
    const float* beta_raw  = (const float*)d_in[3];
    const float* kappa_raw = (const float*)d_in[4];
    const float* C_raw     = (const float*)d_in[5];
    float* out = (float*)d_out;

    cudaFuncSetAttribute(gql_main, cudaFuncAttributeMaxDynamicSharedMemorySize,
                         SMEM_BYTES);

    prep_kernel<<<(T_DIM * B_DIM + 255) / 256, 256>>>(inp);
    gql_main<<<B_DIM, 256, SMEM_BYTES>>>(inp, phi_raw, chi_raw, beta_raw,
                                         kappa_raw, C_raw, out);
}

// round 16
// speedup vs baseline: 1.0655x; 1.0655x over previous
#include <cuda_runtime.h>
#include <cuda_fp16.h>
#include <math.h>

#define T_DIM 2048
#define B_DIM 1024
#define A_DIM 4
#define D_DIM 128
#define P_DIM 256
#define TC    16
#define NCH   (T_DIM / TC)     // 128 chunks of 64 rows
#define LDB   272              // tile row stride in bytes (136 halves)
#define NLOGIT (T_DIM * B_DIM * A_DIM)

// SMEM layout (bytes) — total 73728 => 3 CTAs/SM
#define OFF_SA    0            // 2 x 64 float2 (layout [buf][a][tt])  [0,1024)
#define OFF_BETA  1024         // 128 floats      [1024,1536)
#define OFF_KAPPA 1536         // 128 floats      [1536,2048)
#define OFF_LPART 2048         // 4 x 64 floats   [2048,3072)
#define OFF_CT    4096         // 128 x 272 = 34816  [4096,38912)
#define OFF_HS    38912        // 64 x 272 = 17408   [38912,56320)
#define OFF_QS    56320        // 17408              [56320,73728)
#define SMEM_BYTES 73728

// scratch: per (b,t,a): (s = r*a, a)
__device__ float2 g_SA[(size_t)B_DIM * T_DIM * A_DIM];

static __device__ __forceinline__ float nan0(float x) { return (x == x) ? x : 0.0f; }
static __device__ __forceinline__ float clipf(float x, float lo, float hi) {
    return fminf(fmaxf(x, lo), hi);
}
static __device__ __forceinline__ unsigned smem_u32(const void* p) {
    return (unsigned)__cvta_generic_to_shared(p);
}

__global__ void prep_kernel(const float* __restrict__ inp) {
    int gid = blockIdx.x * blockDim.x + threadIdx.x;
    if (gid >= T_DIM * B_DIM) return;
    int b = gid % B_DIM;
    int t = gid / B_DIM;
    const float* row = inp + ((size_t)t * B_DIM + b) * 9;
    float2* o = g_SA + ((size_t)b * T_DIM + t) * A_DIM;
#pragma unroll
    for (int a = 0; a < A_DIM; a++) {
        float act = nan0(row[a]);
        float r   = nan0(row[4 + a]);
        o[a] = make_float2(r * act, act);
    }
}

static __device__ __forceinline__ void mma16816(float* acc, const unsigned* a,
                                                unsigned b0, unsigned b1) {
    asm volatile(
        "mma.sync.aligned.m16n8k16.row.col.f32.f16.f16.f32 "
        "{%0,%1,%2,%3}, {%4,%5,%6,%7}, {%8,%9}, {%0,%1,%2,%3};\n"
        : "+f"(acc[0]), "+f"(acc[1]), "+f"(acc[2]), "+f"(acc[3])
        : "r"(a[0]), "r"(a[1]), "r"(a[2]), "r"(a[3]), "r"(b0), "r"(b1));
}
static __device__ __forceinline__ void ldsm4(unsigned* r, unsigned addr) {
    asm volatile(
        "ldmatrix.sync.aligned.m8n8.x4.shared.b16 {%0,%1,%2,%3}, [%4];\n"
        : "=r"(r[0]), "=r"(r[1]), "=r"(r[2]), "=r"(r[3]) : "r"(addr));
}

// ---------------------------------------------------------------------------
// ONE CTA per b, 256 threads (8 warps), 3 CTAs/SM (smem 72KB, regs<=85).
// TC=16 (64-row chunks), SINGLE-buffered tiles, phased scan -> GEMM.
// Warp tile 32 rows (mwg=w&1) x 32 cols (nwg=w>>1); B from SMEM; kappa
// in the epilogue (symmetric warps).  Cross-CTA phase drift = overlap.
// sa tile stored [a][tt] so the scan reads one float4 per 2 timesteps.
// ---------------------------------------------------------------------------
__global__ void __launch_bounds__(256, 3) gql_main(
    const float* __restrict__ inp,
    const float* __restrict__ phi_raw,  const float* __restrict__ chi_raw,
    const float* __restrict__ beta_raw, const float* __restrict__ kappa_raw,
    const float* __restrict__ C_raw,    float* __restrict__ out) {
    extern __shared__ char sm[];
    float2* sa_s    = (float2*)(sm + OFF_SA);
    float*  beta_s  = (float*)(sm + OFF_BETA);
    float*  kappa_s = (float*)(sm + OFF_KAPPA);
    float*  lpart   = (float*)(sm + OFF_LPART);
    __half* Ct      = (__half*)(sm + OFF_CT);

    const int b    = blockIdx.x;
    const int tid  = threadIdx.x;
    const int lane = tid & 31;
    const int w    = tid >> 5;
    const int g    = lane >> 2;
    const int tg   = lane & 3;
    const int pid  = min(max((int)nan0(__ldg(inp + (size_t)b * 9 + 8)), 0), P_DIM - 1);

    // scan assignment: a = tid>>6, d-pair (d0, d0+1)
    const int aidx = tid >> 6;
    const int d2   = tid & 63;
    const int d0   = d2 * 2;

    float phr0 = phi_raw[pid * D_DIM + d0], phr1 = phi_raw[pid * D_DIM + d0 + 1];
    float chr0 = chi_raw[pid * D_DIM + d0], chr1 = chi_raw[pid * D_DIM + d0 + 1];
    float phi0 = clipf(1.0f / (1.0f + expf(-phr0)), 0.01f, 0.99f);
    float phi1 = clipf(1.0f / (1.0f + expf(-phr1)), 0.01f, 0.99f);
    float chi0 = clipf(1.0f / (1.0f + expf(-chr0)), 0.01f, 0.99f);
    float chi1 = clipf(1.0f / (1.0f + expf(-chr1)), 0.01f, 0.99f);
    float omp0 = 1.0f - phi0, omp1 = 1.0f - phi1;
    float omc0 = 1.0f - chi0, omc1 = 1.0f - chi1;

    if (tid < 128) {
        float br = beta_raw[pid * D_DIM + tid];
        float sp = fmaxf(br, 0.0f) + log1pf(expf(-fabsf(br)));
        beta_s[tid]  = clipf(sp, 0.1f, 10.0f);
        kappa_s[tid] = clipf(kappa_raw[pid * D_DIM + tid], -10.0f, 10.0f);
    }
    // Ct[e][d] = clip(C[d][e])  (col-major B operand), stays in SMEM
    for (int i = tid; i < D_DIM * D_DIM; i += 256) {
        int d = i >> 7, e = i & 127;
        Ct[e * 136 + d] = __float2half(clipf(C_raw[(size_t)pid * (D_DIM * D_DIM) + i],
                                             -10.0f, 10.0f));
    }

    // preload sa chunk 0 into buf 0 (transposed: [a][tt])
    const float2* sa_src = g_SA + (size_t)b * T_DIM * A_DIM;
    if (tid < 64) sa_s[(tid & 3) * 16 + (tid >> 2)] = sa_src[tid];
    __syncthreads();

    // warp tiling + fragment addresses
    const int mwg = w & 1;
    const int nwg = w >> 1;
    const unsigned amt = smem_u32(sm + OFF_HS)
        + (unsigned)((mwg * 32 + (lane & 15)) * LDB + ((lane & 16) ? 16 : 0));
    const unsigned bb = smem_u32(Ct)
        + (unsigned)((nwg * 32 + (lane & 7) + ((lane & 16) ? 8 : 0)) * LDB
                     + ((lane & 8) ? 16 : 0));
    const unsigned hb = smem_u32(sm + OFF_HS) + (unsigned)((mwg * 32 + lane) * LDB);

    float q0 = 0.5f, q1 = 0.5f, h0 = 0.0f, h1 = 0.0f;

    for (int c = 0; c < NCH; c++) {
        const int cb = c & 1;
        float2 nxt;
        const bool pf = (tid < 64) && (c + 1 < NCH);
        if (pf) nxt = __ldg(sa_src + (c + 1) * 64 + tid);

        // ---- scan phase: fp32 state -> f16 tiles (float4 = 2 timesteps) ----
        {
            char* Hw = sm + OFF_HS + d2 * 4 + aidx * LDB;
            char* Qw = sm + OFF_QS + d2 * 4 + aidx * LDB;
            const float4* sab = (const float4*)(sa_s + cb * 64 + aidx * 16);
#pragma unroll
            for (int tp = 0; tp < TC / 2; tp++) {
                float4 sa2 = sab[tp];
                q0 = omp0 * q0 + phi0 * sa2.x;
                q1 = omp1 * q1 + phi1 * sa2.x;
                h0 = omc0 * h0 + chi0 * sa2.y;
                h1 = omc1 * h1 + chi1 * sa2.y;
                *(__half2*)(Hw + (tp * 8) * LDB) = __floats2half2_rn(h0, h1);
                *(__half2*)(Qw + (tp * 8) * LDB) = __floats2half2_rn(q0, q1);
                q0 = omp0 * q0 + phi0 * sa2.z;
                q1 = omp1 * q1 + phi1 * sa2.z;
                h0 = omc0 * h0 + chi0 * sa2.w;
                h1 = omc1 * h1 + chi1 * sa2.w;
                *(__half2*)(Hw + (tp * 8 + 4) * LDB) = __floats2half2_rn(h0, h1);
                *(__half2*)(Qw + (tp * 8 + 4) * LDB) = __floats2half2_rn(q0, q1);
            }
        }
        if (pf) sa_s[(cb ^ 1) * 64 + (tid & 3) * 16 + (tid >> 2)] = nxt;
        __syncthreads();   // tiles + next sa ready

        // ---- GEMM: 32x32 warp tile over this chunk's 64x128 U ----
        float acc[2][4][4];
#pragma unroll
        for (int mt = 0; mt < 2; mt++)
#pragma unroll
            for (int nt = 0; nt < 4; nt++)
#pragma unroll
                for (int i = 0; i < 4; i++) acc[mt][nt][i] = 0.0f;

#pragma unroll
        for (int ks = 0; ks < 8; ks++) {
            unsigned af0[4], af1[4], bf[4];
            ldsm4(af0, amt + ks * 32);
            ldsm4(af1, amt + 16 * LDB + ks * 32);
            ldsm4(bf, bb + ks * 32);
            mma16816(acc[0][0], af0, bf[0], bf[1]);
            mma16816(acc[0][1], af0, bf[2], bf[3]);
            mma16816(acc[1][0], af1, bf[0], bf[1]);
            mma16816(acc[1][1], af1, bf[2], bf[3]);
            ldsm4(bf, bb + 16 * LDB + ks * 32);
            mma16816(acc[0][2], af0, bf[0], bf[1]);
            mma16816(acc[0][3], af0, bf[2], bf[3]);
            mma16816(acc[1][2], af1, bf[0], bf[1]);
            mma16816(acc[1][3], af1, bf[2], bf[3]);
        }

        // ---- epilogue: logit partials over this warp's 32 cols ----
        float pl0[2] = {0.f, 0.f}, pl1[2] = {0.f, 0.f};
#pragma unroll
        for (int nt = 0; nt < 4; nt++) {
            int col = nwg * 32 + nt * 8;
            float2 bet = make_float2(beta_s[col + 2 * tg], beta_s[col + 2 * tg + 1]);
            float2 kap = make_float2(kappa_s[col + 2 * tg], kappa_s[col + 2 * tg + 1]);
            unsigned qf[4], hf[4];
            ldsm4(qf, hb + (OFF_QS - OFF_HS) + (unsigned)(col * 2));
            ldsm4(hf, hb + (unsigned)(col * 2));
#pragma unroll
            for (int mt = 0; mt < 2; mt++) {
                float2 qv0 = __half22float2(*(__half2*)&qf[2 * mt]);
                float2 qv1 = __half22float2(*(__half2*)&qf[2 * mt + 1]);
                float2 hv0 = __half22float2(*(__half2*)&hf[2 * mt]);
                float2 hv1 = __half22float2(*(__half2*)&hf[2 * mt + 1]);
                pl0[mt] += (acc[mt][nt][0] + bet.x) * qv0.x
                         + (acc[mt][nt][1] + bet.y) * qv0.y
                         + kap.x * hv0.x + kap.y * hv0.y;
                pl1[mt] += (acc[mt][nt][2] + bet.x) * qv1.x
                         + (acc[mt][nt][3] + bet.y) * qv1.y
                         + kap.x * hv1.x + kap.y * hv1.y;
            }
        }
#pragma unroll
        for (int mt = 0; mt < 2; mt++) {
            pl0[mt] += __shfl_xor_sync(0xffffffffu, pl0[mt], 1);
            pl0[mt] += __shfl_xor_sync(0xffffffffu, pl0[mt], 2);
            pl1[mt] += __shfl_xor_sync(0xffffffffu, pl1[mt], 1);
            pl1[mt] += __shfl_xor_sync(0xffffffffu, pl1[mt], 2);
            if (tg == 0) {
                int r0 = mwg * 32 + mt * 16 + g;
                lpart[nwg * 64 + r0]     = pl0[mt];
                lpart[nwg * 64 + r0 + 8] = pl1[mt];
            }
        }
        __syncthreads();   // lpart ready; tiles consumed (safe for next scan)

        if (tid < 64) {    // combine 4 col-group partials, store logits
            float lg = (lpart[tid] + lpart[64 + tid])
                     + (lpart[128 + tid] + lpart[192 + tid]);
            int tt = tid >> 2, a = tid & 3;
            out[((size_t)(c * TC + tt) * B_DIM + b) * A_DIM + a] = lg;
        }
        // next lpart write happens only after the next __syncthreads()
    }

    // final q, h: shape (B, A, D)
    float* out_q = out + (size_t)NLOGIT;
    float* out_h = out_q + B_DIM * A_DIM * D_DIM;
    ((float2*)out_q)[(b * A_DIM + aidx) * 64 + d2] = make_float2(q0, q1);
    ((float2*)out_h)[(b * A_DIM + aidx) * 64 + d2] = make_float2(h0, h1);
}

extern "C" void kernel_launch(void* const* d_in, const int* in_sizes, int n_in,
                              void* d_out, int out_size) {
    const float* inp       = (const float*)d_in[0];
    const float* phi_raw   = (const float*)d_in[1];
    const float* chi_raw   = (const float*)d_in[2];
    const float* beta_raw  = (const float*)d_in[3];
    const float* kappa_raw = (const float*)d_in[4];
    const float* C_raw     = (const float*)d_in[5];
    float* out = (float*)d_out;

    cudaFuncSetAttribute(gql_main, cudaFuncAttributeMaxDynamicSharedMemorySize,
                         SMEM_BYTES);

    prep_kernel<<<(T_DIM * B_DIM + 255) / 256, 256>>>(inp);
    gql_main<<<B_DIM, 256, SMEM_BYTES>>>(inp, phi_raw, chi_raw, beta_raw,
                                         kappa_raw, C_raw, out);
}